// round 1
// baseline (speedup 1.0000x reference)
#include <cuda_runtime.h>

// Problem constants
#define B_    8
#define C_    256
#define L_    1024
#define BL    8192            // B*L rows
#define D_IN  512
#define D_ST  16
#define DT_R  16

// ---------------- scratch (static __device__, no allocation) ----------------
__device__ __align__(16) float g_mu[BL];
__device__ __align__(16) float g_rstd[BL];
__device__ __align__(16) float g_xz[BL * 1024];    // [row, 0:512]=xs_pre, [512:1024]=z
__device__ __align__(16) float g_xs[BL * D_IN];    // post conv+silu
__device__ __align__(16) float g_xdbl[BL * 48];    // [dtr(16), Bm(16), Cm(16)]
__device__ __align__(16) float g_dt[BL * D_IN];
__device__ __align__(16) float g_bc[BL * 32];      // packed [Bm(16), Cm(16)]
__device__ __align__(16) float g_yact[BL * D_IN];  // (ys + xs*Dp)*silu(z)

// ---------------- 1. LayerNorm statistics ----------------
// grid (L/32, B), block 256: 8 c-groups x 32 l, coalesced along l.
__global__ __launch_bounds__(256) void meanvar_kernel(const float* __restrict__ x) {
    __shared__ float ss[8][32];
    __shared__ float sq[8][32];
    int b  = blockIdx.y;
    int li = threadIdx.x & 31;
    int cg = threadIdx.x >> 5;
    int l  = blockIdx.x * 32 + li;
    float s = 0.f, q = 0.f;
    const float* xb = x + ((size_t)b * C_ + cg * 32) * L_ + l;
#pragma unroll 8
    for (int c = 0; c < 32; ++c) {
        float v = xb[(size_t)c * L_];
        s += v; q += v * v;
    }
    ss[cg][li] = s; sq[cg][li] = q;
    __syncthreads();
    if (cg == 0) {
#pragma unroll
        for (int g = 1; g < 8; ++g) { s += ss[g][li]; q += sq[g][li]; }
        float m   = s * (1.f / C_);
        float var = q * (1.f / C_) - m * m;
        int row = b * L_ + l;
        g_mu[row]   = m;
        g_rstd[row] = rsqrtf(var + 1e-5f);
    }
}

// ---------------- 2. GEMM1 with fused LayerNorm: xz = LN(u) @ W_in ----------------
// M=8192 (rows=b*L+l), N=1024, K=256. 64x64 tile, BK=16, 256 threads, 4x4 micro.
__global__ __launch_bounds__(256) void gemm1_ln_kernel(
    const float* __restrict__ x, const float* __restrict__ ln_w,
    const float* __restrict__ ln_b, const float* __restrict__ W_in) {
    __shared__ float As[16][64];
    __shared__ float Bs[16][64];
    __shared__ float muS[64], rsS[64];

    int n0   = blockIdx.x * 64;
    int row0 = blockIdx.y * 64;
    int tid  = threadIdx.x;
    if (tid < 64) { muS[tid] = g_mu[row0 + tid]; rsS[tid] = g_rstd[row0 + tid]; }
    __syncthreads();

    int b  = row0 >> 10;
    int l0 = row0 & 1023;
    int tm = tid >> 4, tn = tid & 15;
    float acc[4][4] = {};

    for (int k0 = 0; k0 < C_; k0 += 16) {
#pragma unroll
        for (int i = 0; i < 4; ++i) {
            int e  = tid + i * 256;
            int kk = e >> 6, m = e & 63;
            int c  = k0 + kk;
            // A: x[b, c, l] transposed load (coalesced along l) + LN
            float v = x[((size_t)(b * C_ + c)) * L_ + l0 + m];
            As[kk][m] = (v - muS[m]) * rsS[m] * ln_w[c] + ln_b[c];
            // B: W_in[c, n]
            Bs[kk][m] = W_in[(size_t)c * 1024 + n0 + m];
        }
        __syncthreads();
#pragma unroll
        for (int kk = 0; kk < 16; ++kk) {
            float4 a4 = *(const float4*)&As[kk][tm * 4];
            float4 b4 = *(const float4*)&Bs[kk][tn * 4];
            float ar[4] = {a4.x, a4.y, a4.z, a4.w};
            float br[4] = {b4.x, b4.y, b4.z, b4.w};
#pragma unroll
            for (int i = 0; i < 4; ++i)
#pragma unroll
                for (int j = 0; j < 4; ++j) acc[i][j] += ar[i] * br[j];
        }
        __syncthreads();
    }
#pragma unroll
    for (int i = 0; i < 4; ++i) {
        float4 o = make_float4(acc[i][0], acc[i][1], acc[i][2], acc[i][3]);
        *(float4*)&g_xz[(size_t)(row0 + tm * 4 + i) * 1024 + n0 + tn * 4] = o;
    }
}

// ---------------- 3. causal depthwise conv (k=4) + silu ----------------
// grid 8192 (=b*t), block 512 (=d).
__global__ __launch_bounds__(512) void conv_silu_kernel(
    const float* __restrict__ conv_w, const float* __restrict__ conv_b) {
    int bt = blockIdx.x;
    int d  = threadIdx.x;
    int b  = bt >> 10, t = bt & 1023;
    float acc = conv_b[d];
#pragma unroll
    for (int k = 0; k < 4; ++k) {
        int tt = t - 3 + k;
        if (tt >= 0)
            acc += g_xz[((size_t)(b * L_ + tt)) * 1024 + d] * conv_w[d * 4 + k];
    }
    float s = acc / (1.f + __expf(-acc));   // silu
    g_xs[(size_t)bt * D_IN + d] = s;
}

// ---------------- 4. xdbl = xs @ W_x  (8192 x 48, K=512) ----------------
// block handles 16 rows; thread (r, jj) computes j in {jj, jj+16, jj+32}.
__global__ __launch_bounds__(256) void xdbl_kernel(const float* __restrict__ W_x) {
    __shared__ float xsT[16][512];
    int row0 = blockIdx.x * 16;
    for (int i = threadIdx.x; i < 16 * 512; i += 256) {
        int r = i >> 9, k = i & 511;
        xsT[r][k] = g_xs[(size_t)(row0 + r) * D_IN + k];
    }
    __syncthreads();
    int r  = threadIdx.x >> 4;
    int jj = threadIdx.x & 15;
    float a0 = 0.f, a1 = 0.f, a2 = 0.f;
#pragma unroll 4
    for (int k = 0; k < 512; ++k) {
        float v = xsT[r][k];
        const float* w = &W_x[k * 48 + jj];
        a0 += v * w[0];
        a1 += v * w[16];
        a2 += v * w[32];
    }
    size_t o = (size_t)(row0 + r) * 48 + jj;
    g_xdbl[o]      = a0;
    g_xdbl[o + 16] = a1;
    g_xdbl[o + 32] = a2;
}

// ---------------- 5. dt = softplus(dtr @ W_dt + b_dt); pack Bm/Cm ----------------
// grid 8192 (row), block 512 (d).
__global__ __launch_bounds__(512) void dt_kernel(
    const float* __restrict__ W_dt, const float* __restrict__ b_dt) {
    __shared__ float dtr[16];
    int row = blockIdx.x;
    int tid = threadIdx.x;
    if (tid < 16) dtr[tid] = g_xdbl[(size_t)row * 48 + tid];
    if (tid < 32) g_bc[(size_t)row * 32 + tid] = g_xdbl[(size_t)row * 48 + 16 + tid];
    __syncthreads();
    float a = b_dt[tid];
#pragma unroll
    for (int r = 0; r < 16; ++r) a += dtr[r] * W_dt[r * D_IN + tid];
    float sp = (a > 20.f) ? a : log1pf(__expf(a));
    g_dt[(size_t)row * D_IN + tid] = sp;
}

// ---------------- 6. selective scan (sequential over t) + epilogue ----------------
// grid 512 blocks (64 per batch), block 128 (4 warps). Warp handles 2 channels:
// lanes 0-15 -> d0 (s = lane), lanes 16-31 -> d0+1 (s = lane-16).
__global__ __launch_bounds__(128) void scan_kernel(
    const float* __restrict__ A_log, const float* __restrict__ Dp) {
    int blk   = blockIdx.x;
    int b     = blk >> 6;
    int chunk = blk & 63;
    int warp  = threadIdx.x >> 5;
    int lane  = threadIdx.x & 31;
    int d     = chunk * 8 + warp * 2 + (lane >> 4);
    int s     = lane & 15;

    float A_ds = -__expf(A_log[d * D_ST + s]);
    float Dp_d = Dp[d];
    float h    = 0.f;
    size_t rowBase = (size_t)b * L_;

#pragma unroll 2
    for (int t = 0; t < L_; ++t) {
        size_t row = rowBase + t;
        float dtv = g_dt[row * D_IN + d];
        float xsv = g_xs[row * D_IN + d];
        float Bm  = g_bc[row * 32 + s];
        float Cm  = g_bc[row * 32 + 16 + s];
        h = __expf(dtv * A_ds) * h + (dtv * xsv) * Bm;
        float p = h * Cm;
        p += __shfl_xor_sync(0xffffffffu, p, 8);
        p += __shfl_xor_sync(0xffffffffu, p, 4);
        p += __shfl_xor_sync(0xffffffffu, p, 2);
        p += __shfl_xor_sync(0xffffffffu, p, 1);
        if (s == 0) {
            float zv = g_xz[row * 1024 + 512 + d];
            float y  = p + xsv * Dp_d;
            y = y * (zv / (1.f + __expf(-zv)));   // * silu(z)
            g_yact[row * D_IN + d] = y;
        }
    }
}

// ---------------- 7. GEMM3: out = yact @ W_out, stored transposed (B,C,L) ----------------
// M=8192, N=256, K=512. A tile stored m-major in smem (conflict-free).
__global__ __launch_bounds__(256) void gemm3_kernel(
    const float* __restrict__ W_out, float* __restrict__ out) {
    __shared__ float Asm[64][16];
    __shared__ float Bs[16][64];
    __shared__ float Cs[64][65];

    int n0   = blockIdx.x * 64;
    int row0 = blockIdx.y * 64;
    int tid  = threadIdx.x;
    int b    = row0 >> 10;
    int l0   = row0 & 1023;
    int tm   = tid >> 4, tn = tid & 15;
    float acc[4][4] = {};

    for (int k0 = 0; k0 < D_IN; k0 += 16) {
#pragma unroll
        for (int i = 0; i < 4; ++i) {
            int e = tid + i * 256;
            {   // A: yact[row, k] — 16 consecutive k per row (64B segments)
                int m = e >> 4, kk = e & 15;
                Asm[m][kk] = g_yact[(size_t)(row0 + m) * D_IN + k0 + kk];
            }
            {   // B: W_out[k, n] — coalesced along n
                int kk = e >> 6, n = e & 63;
                Bs[kk][n] = W_out[(size_t)(k0 + kk) * C_ + n0 + n];
            }
        }
        __syncthreads();
#pragma unroll
        for (int kk = 0; kk < 16; ++kk) {
            float4 b4 = *(const float4*)&Bs[kk][tn * 4];
            float br[4] = {b4.x, b4.y, b4.z, b4.w};
            float ar[4];
#pragma unroll
            for (int i = 0; i < 4; ++i) ar[i] = Asm[tm * 4 + i][kk];
#pragma unroll
            for (int i = 0; i < 4; ++i)
#pragma unroll
                for (int j = 0; j < 4; ++j) acc[i][j] += ar[i] * br[j];
        }
        __syncthreads();
    }

    // stage to smem, then write transposed: out[(b*C + n)*L + l], coalesced along l
#pragma unroll
    for (int i = 0; i < 4; ++i)
#pragma unroll
        for (int j = 0; j < 4; ++j) Cs[tm * 4 + i][tn * 4 + j] = acc[i][j];
    __syncthreads();
#pragma unroll
    for (int rep = 0; rep < 16; ++rep) {
        int n = rep * 4 + (tid >> 6);
        int m = tid & 63;
        out[((size_t)(b * C_ + n0 + n)) * L_ + l0 + m] = Cs[m][n];
    }
}

// ---------------- launch ----------------
extern "C" void kernel_launch(void* const* d_in, const int* in_sizes, int n_in,
                              void* d_out, int out_size) {
    const float* x      = (const float*)d_in[0];
    const float* ln_w   = (const float*)d_in[1];
    const float* ln_b   = (const float*)d_in[2];
    const float* W_in   = (const float*)d_in[3];
    const float* conv_w = (const float*)d_in[4];
    const float* conv_b = (const float*)d_in[5];
    const float* W_x    = (const float*)d_in[6];
    const float* W_dt   = (const float*)d_in[7];
    const float* b_dt   = (const float*)d_in[8];
    const float* A_log  = (const float*)d_in[9];
    const float* Dp     = (const float*)d_in[10];
    const float* W_out  = (const float*)d_in[11];
    float* out = (float*)d_out;

    meanvar_kernel<<<dim3(L_ / 32, B_), 256>>>(x);
    gemm1_ln_kernel<<<dim3(1024 / 64, BL / 64), 256>>>(x, ln_w, ln_b, W_in);
    conv_silu_kernel<<<BL, 512>>>(conv_w, conv_b);
    xdbl_kernel<<<BL / 16, 256>>>(W_x);
    dt_kernel<<<BL, 512>>>(W_dt, b_dt);
    scan_kernel<<<512, 128>>>(A_log, Dp);
    gemm3_kernel<<<dim3(C_ / 64, BL / 64), 256>>>(W_out, out);
}

// round 2
// speedup vs baseline: 1.0449x; 1.0449x over previous
#include <cuda_runtime.h>

// Problem constants
#define B_    8
#define C_    256
#define L_    1024
#define BL    8192            // B*L rows
#define D_IN  512
#define D_ST  16
#define DT_R  16

// ---------------- scratch (static __device__, no allocation) ----------------
__device__ __align__(16) float g_mu[BL];
__device__ __align__(16) float g_rstd[BL];
__device__ __align__(16) float g_xz[BL * 1024];    // [row, 0:512]=xs_pre, [512:1024]=z
__device__ __align__(16) float g_xs[BL * D_IN];    // post conv+silu
__device__ __align__(16) float g_xdbl[BL * 48];    // [dtr(16), Bm(16), Cm(16)]
__device__ __align__(16) float g_dt[BL * D_IN];
__device__ __align__(16) float g_bc[BL * 32];      // packed [Bm(16), Cm(16)]
__device__ __align__(16) float g_yact[BL * D_IN];  // (ys + xs*Dp)*silu(z)

// ---------------- 1. LayerNorm statistics ----------------
__global__ __launch_bounds__(256) void meanvar_kernel(const float* __restrict__ x) {
    __shared__ float ss[8][32];
    __shared__ float sq[8][32];
    int b  = blockIdx.y;
    int li = threadIdx.x & 31;
    int cg = threadIdx.x >> 5;
    int l  = blockIdx.x * 32 + li;
    float s = 0.f, q = 0.f;
    const float* xb = x + ((size_t)b * C_ + cg * 32) * L_ + l;
#pragma unroll 8
    for (int c = 0; c < 32; ++c) {
        float v = xb[(size_t)c * L_];
        s += v; q += v * v;
    }
    ss[cg][li] = s; sq[cg][li] = q;
    __syncthreads();
    if (cg == 0) {
#pragma unroll
        for (int g = 1; g < 8; ++g) { s += ss[g][li]; q += sq[g][li]; }
        float m   = s * (1.f / C_);
        float var = q * (1.f / C_) - m * m;
        int row = b * L_ + l;
        g_mu[row]   = m;
        g_rstd[row] = rsqrtf(var + 1e-5f);
    }
}

// ---------------- 2. GEMM1 with fused LayerNorm: xz = LN(u) @ W_in ----------------
// M=8192, N=1024, K=256. 128x128 tile, BK=16, 256 threads, 8x8 micro, double-buffered.
__global__ __launch_bounds__(256) void gemm1_ln_kernel(
    const float* __restrict__ x, const float* __restrict__ ln_w,
    const float* __restrict__ ln_b, const float* __restrict__ W_in) {
    __shared__ float As[2][16][128];
    __shared__ float Bs[2][16][128];
    __shared__ float muS[128], rsS[128];

    const int tid  = threadIdx.x;
    const int n0   = blockIdx.x * 128;
    const int row0 = blockIdx.y * 128;
    if (tid < 128) { muS[tid] = g_mu[row0 + tid]; rsS[tid] = g_rstd[row0 + tid]; }
    __syncthreads();

    const int b  = row0 >> 10;
    const int l0 = row0 & 1023;
    const int tm = tid >> 4, tn = tid & 15;

    // loader: two float4 slots per thread, slot f -> (kk=f>>5, m=(f&31)*4)
    const int kk0 = tid >> 5,           m0 = (tid & 31) * 4;
    const int kk1 = (tid + 256) >> 5,   m1 = ((tid + 256) & 31) * 4;

    float4 pa0, pa1, pb0, pb1;
    float  w0, w1, bb0, bb1;

    auto gload = [&](int k0) {
        int c0 = k0 + kk0, c1 = k0 + kk1;
        pa0 = *(const float4*)&x[((size_t)(b * C_ + c0)) * L_ + l0 + m0];
        pa1 = *(const float4*)&x[((size_t)(b * C_ + c1)) * L_ + l0 + m1];
        w0 = ln_w[c0]; bb0 = ln_b[c0];
        w1 = ln_w[c1]; bb1 = ln_b[c1];
        pb0 = *(const float4*)&W_in[(size_t)c0 * 1024 + n0 + m0];
        pb1 = *(const float4*)&W_in[(size_t)c1 * 1024 + n0 + m1];
    };
    auto sstore = [&](int buf) {
        As[buf][kk0][m0 + 0] = (pa0.x - muS[m0 + 0]) * rsS[m0 + 0] * w0 + bb0;
        As[buf][kk0][m0 + 1] = (pa0.y - muS[m0 + 1]) * rsS[m0 + 1] * w0 + bb0;
        As[buf][kk0][m0 + 2] = (pa0.z - muS[m0 + 2]) * rsS[m0 + 2] * w0 + bb0;
        As[buf][kk0][m0 + 3] = (pa0.w - muS[m0 + 3]) * rsS[m0 + 3] * w0 + bb0;
        As[buf][kk1][m1 + 0] = (pa1.x - muS[m1 + 0]) * rsS[m1 + 0] * w1 + bb1;
        As[buf][kk1][m1 + 1] = (pa1.y - muS[m1 + 1]) * rsS[m1 + 1] * w1 + bb1;
        As[buf][kk1][m1 + 2] = (pa1.z - muS[m1 + 2]) * rsS[m1 + 2] * w1 + bb1;
        As[buf][kk1][m1 + 3] = (pa1.w - muS[m1 + 3]) * rsS[m1 + 3] * w1 + bb1;
        *(float4*)&Bs[buf][kk0][m0] = pb0;
        *(float4*)&Bs[buf][kk1][m1] = pb1;
    };

    float acc[8][8] = {};
    gload(0);
    sstore(0);
    __syncthreads();

    const int NIT = C_ / 16;  // 16
    for (int it = 0; it < NIT; ++it) {
        if (it + 1 < NIT) gload((it + 1) * 16);
        int buf = it & 1;
#pragma unroll
        for (int kk = 0; kk < 16; ++kk) {
            float ar[8], br[8];
            *(float4*)&ar[0] = *(const float4*)&As[buf][kk][tm * 8];
            *(float4*)&ar[4] = *(const float4*)&As[buf][kk][tm * 8 + 4];
            *(float4*)&br[0] = *(const float4*)&Bs[buf][kk][tn * 8];
            *(float4*)&br[4] = *(const float4*)&Bs[buf][kk][tn * 8 + 4];
#pragma unroll
            for (int i = 0; i < 8; ++i)
#pragma unroll
                for (int j = 0; j < 8; ++j) acc[i][j] += ar[i] * br[j];
        }
        if (it + 1 < NIT) sstore(buf ^ 1);
        __syncthreads();
    }

#pragma unroll
    for (int i = 0; i < 8; ++i) {
        size_t row = row0 + tm * 8 + i;
        float4 o0 = make_float4(acc[i][0], acc[i][1], acc[i][2], acc[i][3]);
        float4 o1 = make_float4(acc[i][4], acc[i][5], acc[i][6], acc[i][7]);
        *(float4*)&g_xz[row * 1024 + n0 + tn * 8]     = o0;
        *(float4*)&g_xz[row * 1024 + n0 + tn * 8 + 4] = o1;
    }
}

// ---------------- 3. causal depthwise conv (k=4) + silu ----------------
__global__ __launch_bounds__(512) void conv_silu_kernel(
    const float* __restrict__ conv_w, const float* __restrict__ conv_b) {
    int bt = blockIdx.x;
    int d  = threadIdx.x;
    int b  = bt >> 10, t = bt & 1023;
    float acc = conv_b[d];
#pragma unroll
    for (int k = 0; k < 4; ++k) {
        int tt = t - 3 + k;
        if (tt >= 0)
            acc += g_xz[((size_t)(b * L_ + tt)) * 1024 + d] * conv_w[d * 4 + k];
    }
    float s = acc / (1.f + __expf(-acc));   // silu
    g_xs[(size_t)bt * D_IN + d] = s;
}

// ---------------- 4. xdbl = xs @ W_x (8192 x 48, K=512), W_x staged in smem ----------------
// block = 16 rows, 128 threads; thread (rp=tid>>4 -> rows 2rp,2rp+1; jj=tid&15).
__global__ __launch_bounds__(128) void xdbl_kernel(const float* __restrict__ W_x) {
    __shared__ float xsT[16][512];
    __shared__ float Wxs[64 * 48];
    int row0 = blockIdx.x * 16;
    int tid  = threadIdx.x;
    // load xs tile: 2048 float4, 16 per thread
    for (int i = tid; i < 2048; i += 128) {
        int r = i >> 7, k4 = i & 127;
        *(float4*)&xsT[r][k4 * 4] = *(const float4*)&g_xs[(size_t)(row0 + r) * D_IN + k4 * 4];
    }
    int rp = tid >> 4, jj = tid & 15;
    float a[6] = {};
    for (int kc = 0; kc < 512; kc += 64) {
        __syncthreads();   // xsT ready (1st iter) / prev chunk compute done
        for (int i = tid; i < 768; i += 128)
            *(float4*)&Wxs[i * 4] = *(const float4*)&W_x[kc * 48 + i * 4];
        __syncthreads();
#pragma unroll 4
        for (int k = 0; k < 64; ++k) {
            float v0 = xsT[2 * rp][kc + k];
            float v1 = xsT[2 * rp + 1][kc + k];
            const float* w = &Wxs[k * 48 + jj];
            float w0 = w[0], w1 = w[16], w2 = w[32];
            a[0] += v0 * w0; a[1] += v0 * w1; a[2] += v0 * w2;
            a[3] += v1 * w0; a[4] += v1 * w1; a[5] += v1 * w2;
        }
    }
    size_t o = (size_t)(row0 + 2 * rp) * 48 + jj;
    g_xdbl[o]      = a[0];
    g_xdbl[o + 16] = a[1];
    g_xdbl[o + 32] = a[2];
    o += 48;
    g_xdbl[o]      = a[3];
    g_xdbl[o + 16] = a[4];
    g_xdbl[o + 32] = a[5];
}

// ---------------- 5. dt = softplus(dtr @ W_dt + b_dt); pack Bm/Cm ----------------
__global__ __launch_bounds__(512) void dt_kernel(
    const float* __restrict__ W_dt, const float* __restrict__ b_dt) {
    __shared__ float dtr[16];
    int row = blockIdx.x;
    int tid = threadIdx.x;
    if (tid < 16) dtr[tid] = g_xdbl[(size_t)row * 48 + tid];
    if (tid < 32) g_bc[(size_t)row * 32 + tid] = g_xdbl[(size_t)row * 48 + 16 + tid];
    __syncthreads();
    float a = b_dt[tid];
#pragma unroll
    for (int r = 0; r < 16; ++r) a += dtr[r] * W_dt[r * D_IN + tid];
    float sp = (a > 20.f) ? a : log1pf(__expf(a));
    g_dt[(size_t)row * D_IN + tid] = sp;
}

// ---------------- 6. selective scan (sequential over t) + epilogue ----------------
__global__ __launch_bounds__(128) void scan_kernel(
    const float* __restrict__ A_log, const float* __restrict__ Dp) {
    int blk   = blockIdx.x;
    int b     = blk >> 6;
    int chunk = blk & 63;
    int warp  = threadIdx.x >> 5;
    int lane  = threadIdx.x & 31;
    int d     = chunk * 8 + warp * 2 + (lane >> 4);
    int s     = lane & 15;

    float A_ds = -__expf(A_log[d * D_ST + s]);
    float Dp_d = Dp[d];
    float h    = 0.f;
    size_t rowBase = (size_t)b * L_;

#pragma unroll 4
    for (int t = 0; t < L_; ++t) {
        size_t row = rowBase + t;
        float dtv = g_dt[row * D_IN + d];
        float xsv = g_xs[row * D_IN + d];
        float Bm  = g_bc[row * 32 + s];
        float Cm  = g_bc[row * 32 + 16 + s];
        h = __expf(dtv * A_ds) * h + (dtv * xsv) * Bm;
        float p = h * Cm;
        p += __shfl_xor_sync(0xffffffffu, p, 8);
        p += __shfl_xor_sync(0xffffffffu, p, 4);
        p += __shfl_xor_sync(0xffffffffu, p, 2);
        p += __shfl_xor_sync(0xffffffffu, p, 1);
        if (s == 0) {
            float zv = g_xz[row * 1024 + 512 + d];
            float y  = p + xsv * Dp_d;
            y = y * (zv / (1.f + __expf(-zv)));   // * silu(z)
            g_yact[row * D_IN + d] = y;
        }
    }
}

// ---------------- 7. GEMM3: out = yact @ W_out, stored transposed (B,C,L) ----------------
// M=8192, N=256, K=512. 128x128 tile, 8x8 micro, double-buffered. A is m-major in smem.
__global__ __launch_bounds__(256) void gemm3_kernel(
    const float* __restrict__ W_out, float* __restrict__ out) {
    __shared__ float As2[2][128][17];
    __shared__ float Bs[2][16][128];

    const int tid  = threadIdx.x;
    const int n0   = blockIdx.x * 128;
    const int row0 = blockIdx.y * 128;
    const int b    = row0 >> 10;
    const int l0   = row0 & 1023;
    const int tm   = tid >> 4, tn = tid & 15;

    // A loader: slot f -> (m=f>>2, kq=f&3) -> float4 at k = kq*4
    const int mA0 = tid >> 2,          kqA0 = tid & 3;
    const int mA1 = (tid + 256) >> 2,  kqA1 = (tid + 256) & 3;
    // B loader: slot f -> (kk=f>>5, n=(f&31)*4)
    const int kkB0 = tid >> 5,         nB0 = (tid & 31) * 4;
    const int kkB1 = (tid + 256) >> 5, nB1 = ((tid + 256) & 31) * 4;

    float4 pa0, pa1, pb0, pb1;
    auto gload = [&](int k0) {
        pa0 = *(const float4*)&g_yact[(size_t)(row0 + mA0) * D_IN + k0 + kqA0 * 4];
        pa1 = *(const float4*)&g_yact[(size_t)(row0 + mA1) * D_IN + k0 + kqA1 * 4];
        pb0 = *(const float4*)&W_out[(size_t)(k0 + kkB0) * C_ + n0 + nB0];
        pb1 = *(const float4*)&W_out[(size_t)(k0 + kkB1) * C_ + n0 + nB1];
    };
    auto sstore = [&](int buf) {
        As2[buf][mA0][kqA0 * 4 + 0] = pa0.x;
        As2[buf][mA0][kqA0 * 4 + 1] = pa0.y;
        As2[buf][mA0][kqA0 * 4 + 2] = pa0.z;
        As2[buf][mA0][kqA0 * 4 + 3] = pa0.w;
        As2[buf][mA1][kqA1 * 4 + 0] = pa1.x;
        As2[buf][mA1][kqA1 * 4 + 1] = pa1.y;
        As2[buf][mA1][kqA1 * 4 + 2] = pa1.z;
        As2[buf][mA1][kqA1 * 4 + 3] = pa1.w;
        *(float4*)&Bs[buf][kkB0][nB0] = pb0;
        *(float4*)&Bs[buf][kkB1][nB1] = pb1;
    };

    float acc[8][8] = {};
    gload(0);
    sstore(0);
    __syncthreads();

    const int NIT = D_IN / 16;  // 32
    for (int it = 0; it < NIT; ++it) {
        if (it + 1 < NIT) gload((it + 1) * 16);
        int buf = it & 1;
#pragma unroll
        for (int kk = 0; kk < 16; ++kk) {
            float ar[8], br[8];
#pragma unroll
            for (int i = 0; i < 8; ++i) ar[i] = As2[buf][tm * 8 + i][kk];
            *(float4*)&br[0] = *(const float4*)&Bs[buf][kk][tn * 8];
            *(float4*)&br[4] = *(const float4*)&Bs[buf][kk][tn * 8 + 4];
#pragma unroll
            for (int i = 0; i < 8; ++i)
#pragma unroll
                for (int j = 0; j < 8; ++j) acc[i][j] += ar[i] * br[j];
        }
        if (it + 1 < NIT) sstore(buf ^ 1);
        __syncthreads();
    }

    // write transposed: out[(b*C + n)*L + l0 + m], float4 along m (= i)
#pragma unroll
    for (int j = 0; j < 8; ++j) {
        size_t nrow = (size_t)(b * C_ + n0 + tn * 8 + j) * L_ + l0 + tm * 8;
        float4 o0 = make_float4(acc[0][j], acc[1][j], acc[2][j], acc[3][j]);
        float4 o1 = make_float4(acc[4][j], acc[5][j], acc[6][j], acc[7][j]);
        *(float4*)&out[nrow]     = o0;
        *(float4*)&out[nrow + 4] = o1;
    }
}

// ---------------- launch ----------------
extern "C" void kernel_launch(void* const* d_in, const int* in_sizes, int n_in,
                              void* d_out, int out_size) {
    const float* x      = (const float*)d_in[0];
    const float* ln_w   = (const float*)d_in[1];
    const float* ln_b   = (const float*)d_in[2];
    const float* W_in   = (const float*)d_in[3];
    const float* conv_w = (const float*)d_in[4];
    const float* conv_b = (const float*)d_in[5];
    const float* W_x    = (const float*)d_in[6];
    const float* W_dt   = (const float*)d_in[7];
    const float* b_dt   = (const float*)d_in[8];
    const float* A_log  = (const float*)d_in[9];
    const float* Dp     = (const float*)d_in[10];
    const float* W_out  = (const float*)d_in[11];
    float* out = (float*)d_out;

    meanvar_kernel<<<dim3(L_ / 32, B_), 256>>>(x);
    gemm1_ln_kernel<<<dim3(1024 / 128, BL / 128), 256>>>(x, ln_w, ln_b, W_in);
    conv_silu_kernel<<<BL, 512>>>(conv_w, conv_b);
    xdbl_kernel<<<BL / 16, 128>>>(W_x);
    dt_kernel<<<BL, 512>>>(W_dt, b_dt);
    scan_kernel<<<512, 128>>>(A_log, Dp);
    gemm3_kernel<<<dim3(C_ / 128, BL / 128), 256>>>(W_out, out);
}

// round 3
// speedup vs baseline: 2.2178x; 2.1226x over previous
#include <cuda_runtime.h>

// Problem constants
#define B_    8
#define C_    256
#define L_    1024
#define BL    8192            // B*L rows
#define D_IN  512
#define D_ST  16
#define DT_R  16

typedef unsigned long long ull;

__device__ __forceinline__ ull pack2(float a, float b) {
    ull r; asm("mov.b64 %0, {%1, %2};" : "=l"(r) : "f"(a), "f"(b)); return r;
}
__device__ __forceinline__ float2 unpack2(ull v) {
    float2 r; asm("mov.b64 {%0, %1}, %2;" : "=f"(r.x), "=f"(r.y) : "l"(v)); return r;
}
__device__ __forceinline__ void fma2(ull& d, ull a, ull b) {
    asm("fma.rn.f32x2 %0, %1, %2, %0;" : "+l"(d) : "l"(a), "l"(b));
}

// ---------------- scratch (static __device__, no allocation) ----------------
__device__ __align__(16) float g_mu[BL];
__device__ __align__(16) float g_rstd[BL];
__device__ __align__(16) float g_xz[BL * 1024];    // [row, 0:512]=xs_pre, [512:1024]=z
__device__ __align__(16) float g_xs[BL * D_IN];    // post conv+silu
__device__ __align__(16) float g_xdbl[BL * 48];    // [dtr(16), Bm(16), Cm(16)]
__device__ __align__(16) float g_dt[BL * D_IN];
__device__ __align__(16) float g_bc[BL * 32];      // packed [Bm(16), Cm(16)]
__device__ __align__(16) float g_yact[BL * D_IN];  // (ys + xs*Dp)*silu(z)

// ---------------- 1. LayerNorm statistics ----------------
__global__ __launch_bounds__(256) void meanvar_kernel(const float* __restrict__ x) {
    __shared__ float ss[8][32];
    __shared__ float sq[8][32];
    int b  = blockIdx.y;
    int li = threadIdx.x & 31;
    int cg = threadIdx.x >> 5;
    int l  = blockIdx.x * 32 + li;
    float s = 0.f, q = 0.f;
    const float* xb = x + ((size_t)b * C_ + cg * 32) * L_ + l;
#pragma unroll 8
    for (int c = 0; c < 32; ++c) {
        float v = xb[(size_t)c * L_];
        s += v; q += v * v;
    }
    ss[cg][li] = s; sq[cg][li] = q;
    __syncthreads();
    if (cg == 0) {
#pragma unroll
        for (int g = 1; g < 8; ++g) { s += ss[g][li]; q += sq[g][li]; }
        float m   = s * (1.f / C_);
        float var = q * (1.f / C_) - m * m;
        int row = b * L_ + l;
        g_mu[row]   = m;
        g_rstd[row] = rsqrtf(var + 1e-5f);
    }
}

// ---------------- 2. GEMM1 with fused LayerNorm: xz = LN(u) @ W_in ----------------
// 128x128 tile, BK=16, 256 threads, 8x8 micro via fma.rn.f32x2, double-buffered.
__global__ __launch_bounds__(256) void gemm1_ln_kernel(
    const float* __restrict__ x, const float* __restrict__ ln_w,
    const float* __restrict__ ln_b, const float* __restrict__ W_in) {
    __shared__ float As[2][16][128];
    __shared__ float Bs[2][16][128];
    __shared__ float muS[128], rsS[128];

    const int tid  = threadIdx.x;
    const int n0   = blockIdx.x * 128;
    const int row0 = blockIdx.y * 128;
    if (tid < 128) { muS[tid] = g_mu[row0 + tid]; rsS[tid] = g_rstd[row0 + tid]; }
    __syncthreads();

    const int b  = row0 >> 10;
    const int l0 = row0 & 1023;
    const int tm = tid >> 4, tn = tid & 15;

    const int kk0 = tid >> 5,           m0 = (tid & 31) * 4;
    const int kk1 = (tid + 256) >> 5,   m1 = ((tid + 256) & 31) * 4;

    float4 pa0, pa1, pb0, pb1;
    float  w0, w1, bb0, bb1;

    auto gload = [&](int k0) {
        int c0 = k0 + kk0, c1 = k0 + kk1;
        pa0 = *(const float4*)&x[((size_t)(b * C_ + c0)) * L_ + l0 + m0];
        pa1 = *(const float4*)&x[((size_t)(b * C_ + c1)) * L_ + l0 + m1];
        w0 = ln_w[c0]; bb0 = ln_b[c0];
        w1 = ln_w[c1]; bb1 = ln_b[c1];
        pb0 = *(const float4*)&W_in[(size_t)c0 * 1024 + n0 + m0];
        pb1 = *(const float4*)&W_in[(size_t)c1 * 1024 + n0 + m1];
    };
    auto sstore = [&](int buf) {
        As[buf][kk0][m0 + 0] = (pa0.x - muS[m0 + 0]) * rsS[m0 + 0] * w0 + bb0;
        As[buf][kk0][m0 + 1] = (pa0.y - muS[m0 + 1]) * rsS[m0 + 1] * w0 + bb0;
        As[buf][kk0][m0 + 2] = (pa0.z - muS[m0 + 2]) * rsS[m0 + 2] * w0 + bb0;
        As[buf][kk0][m0 + 3] = (pa0.w - muS[m0 + 3]) * rsS[m0 + 3] * w0 + bb0;
        As[buf][kk1][m1 + 0] = (pa1.x - muS[m1 + 0]) * rsS[m1 + 0] * w1 + bb1;
        As[buf][kk1][m1 + 1] = (pa1.y - muS[m1 + 1]) * rsS[m1 + 1] * w1 + bb1;
        As[buf][kk1][m1 + 2] = (pa1.z - muS[m1 + 2]) * rsS[m1 + 2] * w1 + bb1;
        As[buf][kk1][m1 + 3] = (pa1.w - muS[m1 + 3]) * rsS[m1 + 3] * w1 + bb1;
        *(float4*)&Bs[buf][kk0][m0] = pb0;
        *(float4*)&Bs[buf][kk1][m1] = pb1;
    };

    ull acc2[8][4];
#pragma unroll
    for (int i = 0; i < 8; ++i)
#pragma unroll
        for (int j = 0; j < 4; ++j) acc2[i][j] = 0ull;

    gload(0);
    sstore(0);
    __syncthreads();

    const int NIT = C_ / 16;  // 16
    for (int it = 0; it < NIT; ++it) {
        if (it + 1 < NIT) gload((it + 1) * 16);
        int buf = it & 1;
#pragma unroll
        for (int kk = 0; kk < 16; ++kk) {
            float ar[8];
            *(float4*)&ar[0] = *(const float4*)&As[buf][kk][tm * 8];
            *(float4*)&ar[4] = *(const float4*)&As[buf][kk][tm * 8 + 4];
            ull br2[4];
            const ull* bp = (const ull*)&Bs[buf][kk][tn * 8];
            br2[0] = bp[0]; br2[1] = bp[1]; br2[2] = bp[2]; br2[3] = bp[3];
#pragma unroll
            for (int i = 0; i < 8; ++i) {
                ull ai = pack2(ar[i], ar[i]);
                fma2(acc2[i][0], ai, br2[0]);
                fma2(acc2[i][1], ai, br2[1]);
                fma2(acc2[i][2], ai, br2[2]);
                fma2(acc2[i][3], ai, br2[3]);
            }
        }
        if (it + 1 < NIT) sstore(buf ^ 1);
        __syncthreads();
    }

#pragma unroll
    for (int i = 0; i < 8; ++i) {
        size_t row = row0 + tm * 8 + i;
        ulonglong2 o0 = make_ulonglong2(acc2[i][0], acc2[i][1]);
        ulonglong2 o1 = make_ulonglong2(acc2[i][2], acc2[i][3]);
        *(ulonglong2*)&g_xz[row * 1024 + n0 + tn * 8]     = o0;
        *(ulonglong2*)&g_xz[row * 1024 + n0 + tn * 8 + 4] = o1;
    }
}

// ---------------- 3. causal depthwise conv (k=4) + silu ----------------
__global__ __launch_bounds__(512) void conv_silu_kernel(
    const float* __restrict__ conv_w, const float* __restrict__ conv_b) {
    int bt = blockIdx.x;
    int d  = threadIdx.x;
    int b  = bt >> 10, t = bt & 1023;
    float acc = conv_b[d];
#pragma unroll
    for (int k = 0; k < 4; ++k) {
        int tt = t - 3 + k;
        if (tt >= 0)
            acc += g_xz[((size_t)(b * L_ + tt)) * 1024 + d] * conv_w[d * 4 + k];
    }
    float s = acc / (1.f + __expf(-acc));   // silu
    g_xs[(size_t)bt * D_IN + d] = s;
}

// ---------------- 4. xdbl = xs @ W_x (8192 x 48, K=512) ----------------
// block = 32 rows, 128 threads; thread handles 4 rows x 3 outputs.
__global__ __launch_bounds__(128) void xdbl_kernel(const float* __restrict__ W_x) {
    __shared__ float xsT[32][64];
    __shared__ float Wxs[64 * 48];
    int row0 = blockIdx.x * 32;
    int tid  = threadIdx.x;
    int rp = tid >> 4, jj = tid & 15;   // rows 4rp..4rp+3
    float a[12] = {};
    for (int kc = 0; kc < 512; kc += 64) {
        __syncthreads();
        // stage W_x chunk: 64x48 = 768 float4 / 128 threads = 6 each
#pragma unroll
        for (int i = 0; i < 6; ++i) {
            int e = tid + i * 128;
            *(float4*)&Wxs[e * 4] = *(const float4*)&W_x[kc * 48 + e * 4];
        }
        // stage xs chunk: 32 rows x 64 k = 512 float4 / 128 = 4 each
#pragma unroll
        for (int i = 0; i < 4; ++i) {
            int e = tid + i * 128;
            int r = e >> 4, k4 = e & 15;
            *(float4*)&xsT[r][k4 * 4] =
                *(const float4*)&g_xs[(size_t)(row0 + r) * D_IN + kc + k4 * 4];
        }
        __syncthreads();
#pragma unroll 4
        for (int k = 0; k < 64; ++k) {
            const float* w = &Wxs[k * 48 + jj];
            float w0 = w[0], w1 = w[16], w2 = w[32];
#pragma unroll
            for (int q = 0; q < 4; ++q) {
                float v = xsT[4 * rp + q][k];
                a[3 * q + 0] += v * w0;
                a[3 * q + 1] += v * w1;
                a[3 * q + 2] += v * w2;
            }
        }
    }
#pragma unroll
    for (int q = 0; q < 4; ++q) {
        size_t o = (size_t)(row0 + 4 * rp + q) * 48 + jj;
        g_xdbl[o]      = a[3 * q + 0];
        g_xdbl[o + 16] = a[3 * q + 1];
        g_xdbl[o + 32] = a[3 * q + 2];
    }
}

// ---------------- 5. dt = softplus(dtr @ W_dt + b_dt); pack Bm/Cm ----------------
// block = 16 rows, 256 threads, W_dt staged in smem (L2 traffic /16).
__global__ __launch_bounds__(256) void dt_kernel(
    const float* __restrict__ W_dt, const float* __restrict__ b_dt) {
    __shared__ float Wd[16][512];
    __shared__ float dtrS[16][16];
    int row0 = blockIdx.x * 16;
    int tid  = threadIdx.x;
    // stage W_dt: 16*512 = 2048 float4... = 8192 floats = 2048 float4 / 256 = 8 each
#pragma unroll
    for (int i = 0; i < 8; ++i) {
        int e = tid + i * 256;          // float4 index
        int r = e >> 7, k4 = e & 127;
        *(float4*)&Wd[r][k4 * 4] = *(const float4*)&W_dt[(size_t)r * D_IN + k4 * 4];
    }
    // stage dtr + write bc: 16 rows x 48
    for (int e = tid; e < 16 * 48; e += 256) {
        int r = e / 48, c = e % 48;
        float v = g_xdbl[(size_t)(row0 + r) * 48 + c];
        if (c < 16) dtrS[r][c] = v;
        else        g_bc[(size_t)(row0 + r) * 32 + (c - 16)] = v;
    }
    __syncthreads();
    int r     = tid >> 4;
    int dbase = tid & 15;
    float dr[16];
#pragma unroll
    for (int rr = 0; rr < 16; ++rr) dr[rr] = dtrS[r][rr];
    size_t orow = (size_t)(row0 + r) * D_IN;
#pragma unroll 4
    for (int k = 0; k < 32; ++k) {
        int dd = dbase + k * 16;
        float a = b_dt[dd];
#pragma unroll
        for (int rr = 0; rr < 16; ++rr) a += dr[rr] * Wd[rr][dd];
        float sp = (a > 20.f) ? a : log1pf(__expf(a));
        g_dt[orow + dd] = sp;
    }
}

// ---------------- 6. selective scan, smem-staged in 64-step chunks ----------------
// grid 512 (64 chunks per batch x 8 channels), block 128 (4 warps).
// Warp handles 2 channels: lanes 0-15 -> d0 (s=lane), 16-31 -> d0+1.
#define TCH 64
__global__ __launch_bounds__(128) void scan_kernel(
    const float* __restrict__ A_log, const float* __restrict__ Dp) {
    __shared__ float s_dt[TCH][8];
    __shared__ float s_xs[TCH][8];
    __shared__ float s_z[TCH][8];
    __shared__ float s_bc[TCH][32];

    int blk   = blockIdx.x;
    int b     = blk >> 6;
    int chunk = blk & 63;
    int d0    = chunk * 8;
    int tid   = threadIdx.x;
    int warp  = tid >> 5;
    int lane  = tid & 31;
    int jd    = warp * 2 + (lane >> 4);   // 0..7 local channel
    int d     = d0 + jd;
    int s     = lane & 15;

    float A_ds = -__expf(A_log[d * D_ST + s]);
    float Dp_d = Dp[d];
    float h    = 0.f;
    size_t rowBase = (size_t)b * L_;

    for (int t0 = 0; t0 < L_; t0 += TCH) {
        __syncthreads();  // protect smem reuse from previous chunk
#pragma unroll
        for (int i = 0; i < 4; ++i) {
            int e = tid + i * 128;
            int t = e >> 3, j = e & 7;
            size_t row = rowBase + t0 + t;
            s_dt[t][j] = g_dt[row * D_IN + d0 + j];
            s_xs[t][j] = g_xs[row * D_IN + d0 + j];
            s_z[t][j]  = g_xz[row * 1024 + 512 + d0 + j];
        }
#pragma unroll
        for (int i = 0; i < 16; ++i) {
            int e = tid + i * 128;
            int t = e >> 5, sj = e & 31;
            s_bc[t][sj] = g_bc[(rowBase + t0 + t) * 32 + sj];
        }
        __syncthreads();
#pragma unroll 4
        for (int tt = 0; tt < TCH; ++tt) {
            float dtv = s_dt[tt][jd];
            float xsv = s_xs[tt][jd];
            float Bm  = s_bc[tt][s];
            float Cm  = s_bc[tt][16 + s];
            h = __expf(dtv * A_ds) * h + (dtv * xsv) * Bm;
            float p = h * Cm;
            p += __shfl_xor_sync(0xffffffffu, p, 8);
            p += __shfl_xor_sync(0xffffffffu, p, 4);
            p += __shfl_xor_sync(0xffffffffu, p, 2);
            p += __shfl_xor_sync(0xffffffffu, p, 1);
            if (s == 0) {
                float zv = s_z[tt][jd];
                float y  = p + xsv * Dp_d;
                y = y * (zv / (1.f + __expf(-zv)));
                g_yact[(rowBase + t0 + tt) * D_IN + d] = y;
            }
        }
    }
}

// ---------------- 7. GEMM3: out = yact @ W_out, stored transposed (B,C,L) ----------------
// 128x128 tile, 8x8 micro via fma.rn.f32x2 (pairs along m), double-buffered.
__global__ __launch_bounds__(256) void gemm3_kernel(
    const float* __restrict__ W_out, float* __restrict__ out) {
    __shared__ float As2[2][128][17];
    __shared__ float Bs[2][16][128];

    const int tid  = threadIdx.x;
    const int n0   = blockIdx.x * 128;
    const int row0 = blockIdx.y * 128;
    const int b    = row0 >> 10;
    const int l0   = row0 & 1023;
    const int tm   = tid >> 4, tn = tid & 15;

    const int mA0 = tid >> 2,          kqA0 = tid & 3;
    const int mA1 = (tid + 256) >> 2,  kqA1 = (tid + 256) & 3;
    const int kkB0 = tid >> 5,         nB0 = (tid & 31) * 4;
    const int kkB1 = (tid + 256) >> 5, nB1 = ((tid + 256) & 31) * 4;

    float4 pa0, pa1, pb0, pb1;
    auto gload = [&](int k0) {
        pa0 = *(const float4*)&g_yact[(size_t)(row0 + mA0) * D_IN + k0 + kqA0 * 4];
        pa1 = *(const float4*)&g_yact[(size_t)(row0 + mA1) * D_IN + k0 + kqA1 * 4];
        pb0 = *(const float4*)&W_out[(size_t)(k0 + kkB0) * C_ + n0 + nB0];
        pb1 = *(const float4*)&W_out[(size_t)(k0 + kkB1) * C_ + n0 + nB1];
    };
    auto sstore = [&](int buf) {
        As2[buf][mA0][kqA0 * 4 + 0] = pa0.x;
        As2[buf][mA0][kqA0 * 4 + 1] = pa0.y;
        As2[buf][mA0][kqA0 * 4 + 2] = pa0.z;
        As2[buf][mA0][kqA0 * 4 + 3] = pa0.w;
        As2[buf][mA1][kqA1 * 4 + 0] = pa1.x;
        As2[buf][mA1][kqA1 * 4 + 1] = pa1.y;
        As2[buf][mA1][kqA1 * 4 + 2] = pa1.z;
        As2[buf][mA1][kqA1 * 4 + 3] = pa1.w;
        *(float4*)&Bs[buf][kkB0][nB0] = pb0;
        *(float4*)&Bs[buf][kkB1][nB1] = pb1;
    };

    ull acc2[4][8];   // pairs along m (i), scalar along n (j)
#pragma unroll
    for (int q = 0; q < 4; ++q)
#pragma unroll
        for (int j = 0; j < 8; ++j) acc2[q][j] = 0ull;

    gload(0);
    sstore(0);
    __syncthreads();

    const int NIT = D_IN / 16;  // 32
    for (int it = 0; it < NIT; ++it) {
        if (it + 1 < NIT) gload((it + 1) * 16);
        int buf = it & 1;
#pragma unroll
        for (int kk = 0; kk < 16; ++kk) {
            float ar[8], br[8];
#pragma unroll
            for (int i = 0; i < 8; ++i) ar[i] = As2[buf][tm * 8 + i][kk];
            *(float4*)&br[0] = *(const float4*)&Bs[buf][kk][tn * 8];
            *(float4*)&br[4] = *(const float4*)&Bs[buf][kk][tn * 8 + 4];
            ull ap[4];
#pragma unroll
            for (int q = 0; q < 4; ++q) ap[q] = pack2(ar[2 * q], ar[2 * q + 1]);
#pragma unroll
            for (int j = 0; j < 8; ++j) {
                ull bj = pack2(br[j], br[j]);
                fma2(acc2[0][j], ap[0], bj);
                fma2(acc2[1][j], ap[1], bj);
                fma2(acc2[2][j], ap[2], bj);
                fma2(acc2[3][j], ap[3], bj);
            }
        }
        if (it + 1 < NIT) sstore(buf ^ 1);
        __syncthreads();
    }

    // write transposed: out[(b*C + n)*L + l0 + m], float4 along m
#pragma unroll
    for (int j = 0; j < 8; ++j) {
        size_t nrow = (size_t)(b * C_ + n0 + tn * 8 + j) * L_ + l0 + tm * 8;
        float2 p0 = unpack2(acc2[0][j]);
        float2 p1 = unpack2(acc2[1][j]);
        float2 p2 = unpack2(acc2[2][j]);
        float2 p3 = unpack2(acc2[3][j]);
        *(float4*)&out[nrow]     = make_float4(p0.x, p0.y, p1.x, p1.y);
        *(float4*)&out[nrow + 4] = make_float4(p2.x, p2.y, p3.x, p3.y);
    }
}

// ---------------- launch ----------------
extern "C" void kernel_launch(void* const* d_in, const int* in_sizes, int n_in,
                              void* d_out, int out_size) {
    const float* x      = (const float*)d_in[0];
    const float* ln_w   = (const float*)d_in[1];
    const float* ln_b   = (const float*)d_in[2];
    const float* W_in   = (const float*)d_in[3];
    const float* conv_w = (const float*)d_in[4];
    const float* conv_b = (const float*)d_in[5];
    const float* W_x    = (const float*)d_in[6];
    const float* W_dt   = (const float*)d_in[7];
    const float* b_dt   = (const float*)d_in[8];
    const float* A_log  = (const float*)d_in[9];
    const float* Dp     = (const float*)d_in[10];
    const float* W_out  = (const float*)d_in[11];
    float* out = (float*)d_out;

    meanvar_kernel<<<dim3(L_ / 32, B_), 256>>>(x);
    gemm1_ln_kernel<<<dim3(1024 / 128, BL / 128), 256>>>(x, ln_w, ln_b, W_in);
    conv_silu_kernel<<<BL, 512>>>(conv_w, conv_b);
    xdbl_kernel<<<BL / 32, 128>>>(W_x);
    dt_kernel<<<BL / 16, 256>>>(W_dt, b_dt);
    scan_kernel<<<512, 128>>>(A_log, Dp);
    gemm3_kernel<<<dim3(C_ / 128, BL / 128), 256>>>(W_out, out);
}

// round 6
// speedup vs baseline: 2.8682x; 1.2933x over previous
#include <cuda_runtime.h>
#include <cstdint>

// Problem constants
#define B_    8
#define C_    256
#define L_    1024
#define BL    8192            // B*L rows
#define D_IN  512
#define D_ST  16
#define DT_R  16
#define PAD   17

__device__ __forceinline__ uint32_t to_tf32(float v) {
    uint32_t r; asm("cvt.rna.tf32.f32 %0, %1;" : "=r"(r) : "f"(v)); return r;
}
// m16n8k8 tf32 MMA, D += A*B
__device__ __forceinline__ void mma8(float* d, const uint32_t* a, const uint32_t* b) {
    asm volatile(
        "mma.sync.aligned.m16n8k8.row.col.f32.tf32.tf32.f32 "
        "{%0,%1,%2,%3}, {%4,%5,%6,%7}, {%8,%9}, {%0,%1,%2,%3};"
        : "+f"(d[0]), "+f"(d[1]), "+f"(d[2]), "+f"(d[3])
        : "r"(a[0]), "r"(a[1]), "r"(a[2]), "r"(a[3]), "r"(b[0]), "r"(b[1]));
}

// ---------------- scratch (static __device__, no allocation) ----------------
__device__ __align__(16) float g_mu[BL];
__device__ __align__(16) float g_rstd[BL];
__device__ __align__(16) float g_xz[BL * 1024];    // [row, 0:512]=xs_pre, [512:1024]=z
__device__ __align__(16) float g_xs[BL * D_IN];    // post conv+silu
__device__ __align__(16) float g_xdbl[BL * 48];    // [dtr(16), Bm(16), Cm(16)]
__device__ __align__(16) float g_dt[BL * D_IN];
__device__ __align__(16) float g_bc[BL * 32];      // packed [Bm(16), Cm(16)]
__device__ __align__(16) float g_yact[BL * D_IN];  // (ys + xs*Dp)*silu(z)

// ---------------- 1. LayerNorm statistics ----------------
__global__ __launch_bounds__(256) void meanvar_kernel(const float* __restrict__ x) {
    __shared__ float ss[8][32];
    __shared__ float sq[8][32];
    int b  = blockIdx.y;
    int li = threadIdx.x & 31;
    int cg = threadIdx.x >> 5;
    int l  = blockIdx.x * 32 + li;
    float s = 0.f, q = 0.f;
    const float* xb = x + ((size_t)b * C_ + cg * 32) * L_ + l;
#pragma unroll 8
    for (int c = 0; c < 32; ++c) {
        float v = xb[(size_t)c * L_];
        s += v; q += v * v;
    }
    ss[cg][li] = s; sq[cg][li] = q;
    __syncthreads();
    if (cg == 0) {
#pragma unroll
        for (int g = 1; g < 8; ++g) { s += ss[g][li]; q += sq[g][li]; }
        float m   = s * (1.f / C_);
        float var = q * (1.f / C_) - m * m;
        int row = b * L_ + l;
        g_mu[row]   = m;
        g_rstd[row] = rsqrtf(var + 1e-5f);
    }
}

// ---------------- 2. GEMM1 (tf32 mma.sync): xz = LN(u) @ W_in ----------------
// M=8192, N=1024, K=256. CTA 128x128, 8 warps (4m x 2n), warp 32x64, BK=16.
__global__ __launch_bounds__(256) void gemm1_mma_kernel(
    const float* __restrict__ x, const float* __restrict__ ln_w,
    const float* __restrict__ ln_b, const float* __restrict__ W_in) {
    __shared__ uint32_t As[2][128][PAD];   // [m][k] tf32 bits
    __shared__ uint32_t Bsm[2][128][PAD];  // [n][k] tf32 bits
    __shared__ float muS[128], rsS[128], lwS[C_], lbS[C_];

    const int tid  = threadIdx.x;
    const int wid  = tid >> 5;
    const int lane = tid & 31;
    const int n0   = blockIdx.x * 128;
    const int row0 = blockIdx.y * 128;
    const int b    = row0 >> 10;
    const int l0   = row0 & 1023;

    if (tid < 128) { muS[tid] = g_mu[row0 + tid]; rsS[tid] = g_rstd[row0 + tid]; }
    lwS[tid] = ln_w[tid]; lbS[tid] = ln_b[tid];
    __syncthreads();

    const int q = lane >> 2, r = lane & 3;
    const int wm = (wid >> 1) * 32, wn = (wid & 1) * 64;

    float ra[8], rb[8];
    auto gload = [&](int kc) {
#pragma unroll
        for (int i = 0; i < 8; ++i) {
            int e = tid + i * 256;
            int m = e & 127, k = e >> 7;
            ra[i] = x[((size_t)(b * C_ + kc + k)) * L_ + l0 + m];
            int n = e & 127;   // same decomposition for B
            rb[i] = W_in[(size_t)(kc + k) * 1024 + n0 + n];
        }
    };
    auto sstore = [&](int buf, int kc) {
#pragma unroll
        for (int i = 0; i < 8; ++i) {
            int e = tid + i * 256;
            int m = e & 127, k = e >> 7;
            int c = kc + k;
            As[buf][m][k]  = to_tf32((ra[i] - muS[m]) * rsS[m] * lwS[c] + lbS[c]);
            Bsm[buf][m][k] = to_tf32(rb[i]);
        }
    };

    float acc[2][8][4] = {};
    gload(0);
    sstore(0, 0);
    __syncthreads();

    const int NIT = C_ / 16;  // 16
    for (int it = 0; it < NIT; ++it) {
        if (it + 1 < NIT) gload((it + 1) * 16);
        int buf = it & 1;
#pragma unroll
        for (int ks = 0; ks < 2; ++ks) {
            const int kk = ks * 8;
            uint32_t af[2][4];
#pragma unroll
            for (int mt = 0; mt < 2; ++mt) {
                int base = wm + mt * 16;
                af[mt][0] = As[buf][base + q][kk + r];
                af[mt][1] = As[buf][base + q + 8][kk + r];
                af[mt][2] = As[buf][base + q][kk + r + 4];
                af[mt][3] = As[buf][base + q + 8][kk + r + 4];
            }
#pragma unroll
            for (int nt = 0; nt < 8; ++nt) {
                uint32_t bf[2];
                bf[0] = Bsm[buf][wn + nt * 8 + q][kk + r];
                bf[1] = Bsm[buf][wn + nt * 8 + q][kk + r + 4];
                mma8(acc[0][nt], af[0], bf);
                mma8(acc[1][nt], af[1], bf);
            }
        }
        if (it + 1 < NIT) sstore(buf ^ 1, (it + 1) * 16);
        __syncthreads();
    }

#pragma unroll
    for (int mt = 0; mt < 2; ++mt) {
        int rowa = row0 + wm + mt * 16 + q;
#pragma unroll
        for (int nt = 0; nt < 8; ++nt) {
            int n = n0 + wn + nt * 8 + 2 * r;
            *(float2*)&g_xz[(size_t)rowa * 1024 + n]       = make_float2(acc[mt][nt][0], acc[mt][nt][1]);
            *(float2*)&g_xz[(size_t)(rowa + 8) * 1024 + n] = make_float2(acc[mt][nt][2], acc[mt][nt][3]);
        }
    }
}

// ---------------- 3. causal depthwise conv (k=4) + silu ----------------
__global__ __launch_bounds__(512) void conv_silu_kernel(
    const float* __restrict__ conv_w, const float* __restrict__ conv_b) {
    int bt = blockIdx.x;
    int d  = threadIdx.x;
    int b  = bt >> 10, t = bt & 1023;
    float acc = conv_b[d];
#pragma unroll
    for (int k = 0; k < 4; ++k) {
        int tt = t - 3 + k;
        if (tt >= 0)
            acc += g_xz[((size_t)(b * L_ + tt)) * 1024 + d] * conv_w[d * 4 + k];
    }
    float s = acc / (1.f + __expf(-acc));   // silu
    g_xs[(size_t)bt * D_IN + d] = s;
}

// ---------------- 4. xdbl = xs @ W_x (8192 x 48, K=512) ----------------
__global__ __launch_bounds__(128) void xdbl_kernel(const float* __restrict__ W_x) {
    __shared__ float xsT[32][64];
    __shared__ float Wxs[64 * 48];
    int row0 = blockIdx.x * 32;
    int tid  = threadIdx.x;
    int rp = tid >> 4, jj = tid & 15;   // rows 4rp..4rp+3
    float a[12] = {};
    for (int kc = 0; kc < 512; kc += 64) {
        __syncthreads();
#pragma unroll
        for (int i = 0; i < 6; ++i) {
            int e = tid + i * 128;
            *(float4*)&Wxs[e * 4] = *(const float4*)&W_x[kc * 48 + e * 4];
        }
#pragma unroll
        for (int i = 0; i < 4; ++i) {
            int e = tid + i * 128;
            int rr = e >> 4, k4 = e & 15;
            *(float4*)&xsT[rr][k4 * 4] =
                *(const float4*)&g_xs[(size_t)(row0 + rr) * D_IN + kc + k4 * 4];
        }
        __syncthreads();
#pragma unroll 4
        for (int k = 0; k < 64; ++k) {
            const float* w = &Wxs[k * 48 + jj];
            float w0 = w[0], w1 = w[16], w2 = w[32];
#pragma unroll
            for (int qq = 0; qq < 4; ++qq) {
                float v = xsT[4 * rp + qq][k];
                a[3 * qq + 0] += v * w0;
                a[3 * qq + 1] += v * w1;
                a[3 * qq + 2] += v * w2;
            }
        }
    }
#pragma unroll
    for (int qq = 0; qq < 4; ++qq) {
        size_t o = (size_t)(row0 + 4 * rp + qq) * 48 + jj;
        g_xdbl[o]      = a[3 * qq + 0];
        g_xdbl[o + 16] = a[3 * qq + 1];
        g_xdbl[o + 32] = a[3 * qq + 2];
    }
}

// ---------------- 5. dt = softplus(dtr @ W_dt + b_dt); pack Bm/Cm ----------------
__global__ __launch_bounds__(256) void dt_kernel(
    const float* __restrict__ W_dt, const float* __restrict__ b_dt) {
    __shared__ float Wd[16][512];
    __shared__ float dtrS[16][16];
    int row0 = blockIdx.x * 16;
    int tid  = threadIdx.x;
#pragma unroll
    for (int i = 0; i < 8; ++i) {
        int e = tid + i * 256;
        int rr = e >> 7, k4 = e & 127;
        *(float4*)&Wd[rr][k4 * 4] = *(const float4*)&W_dt[(size_t)rr * D_IN + k4 * 4];
    }
    for (int e = tid; e < 16 * 48; e += 256) {
        int rr = e / 48, c = e % 48;
        float v = g_xdbl[(size_t)(row0 + rr) * 48 + c];
        if (c < 16) dtrS[rr][c] = v;
        else        g_bc[(size_t)(row0 + rr) * 32 + (c - 16)] = v;
    }
    __syncthreads();
    int rr    = tid >> 4;
    int dbase = tid & 15;
    float dr[16];
#pragma unroll
    for (int k = 0; k < 16; ++k) dr[k] = dtrS[rr][k];
    size_t orow = (size_t)(row0 + rr) * D_IN;
#pragma unroll 4
    for (int k = 0; k < 32; ++k) {
        int dd = dbase + k * 16;
        float a = b_dt[dd];
#pragma unroll
        for (int j = 0; j < 16; ++j) a += dr[j] * Wd[j][dd];
        float sp = (a > 20.f) ? a : log1pf(__expf(a));
        g_dt[orow + dd] = sp;
    }
}

// ---------------- 6. selective scan, smem-staged in 64-step chunks ----------------
#define TCH 64
__global__ __launch_bounds__(128) void scan_kernel(
    const float* __restrict__ A_log, const float* __restrict__ Dp) {
    __shared__ float s_dt[TCH][8];
    __shared__ float s_xs[TCH][8];
    __shared__ float s_z[TCH][8];
    __shared__ float s_bc[TCH][32];

    int blk   = blockIdx.x;
    int b     = blk >> 6;
    int chunk = blk & 63;
    int d0    = chunk * 8;
    int tid   = threadIdx.x;
    int warp  = tid >> 5;
    int lane  = tid & 31;
    int jd    = warp * 2 + (lane >> 4);   // 0..7 local channel
    int d     = d0 + jd;
    int s     = lane & 15;

    float A_ds = -__expf(A_log[d * D_ST + s]);
    float Dp_d = Dp[d];
    float h    = 0.f;
    size_t rowBase = (size_t)b * L_;

    for (int t0 = 0; t0 < L_; t0 += TCH) {
        __syncthreads();
#pragma unroll
        for (int i = 0; i < 4; ++i) {
            int e = tid + i * 128;
            int t = e >> 3, j = e & 7;
            size_t row = rowBase + t0 + t;
            s_dt[t][j] = g_dt[row * D_IN + d0 + j];
            s_xs[t][j] = g_xs[row * D_IN + d0 + j];
            s_z[t][j]  = g_xz[row * 1024 + 512 + d0 + j];
        }
#pragma unroll
        for (int i = 0; i < 16; ++i) {
            int e = tid + i * 128;
            int t = e >> 5, sj = e & 31;
            s_bc[t][sj] = g_bc[(rowBase + t0 + t) * 32 + sj];
        }
        __syncthreads();
#pragma unroll 4
        for (int tt = 0; tt < TCH; ++tt) {
            float dtv = s_dt[tt][jd];
            float xsv = s_xs[tt][jd];
            float Bm  = s_bc[tt][s];
            float Cm  = s_bc[tt][16 + s];
            h = __expf(dtv * A_ds) * h + (dtv * xsv) * Bm;
            float p = h * Cm;
            p += __shfl_xor_sync(0xffffffffu, p, 8);
            p += __shfl_xor_sync(0xffffffffu, p, 4);
            p += __shfl_xor_sync(0xffffffffu, p, 2);
            p += __shfl_xor_sync(0xffffffffu, p, 1);
            if (s == 0) {
                float zv = s_z[tt][jd];
                float y  = p + xsv * Dp_d;
                y = y * (zv / (1.f + __expf(-zv)));
                g_yact[(rowBase + t0 + tt) * D_IN + d] = y;
            }
        }
    }
}

// ---------------- 7. GEMM3 (tf32 mma.sync): out = yact @ W_out, transposed store ----------------
// M=8192, N=256, K=512. CTA 128x128, 8 warps, BK=16.
__global__ __launch_bounds__(256) void gemm3_mma_kernel(
    const float* __restrict__ W_out, float* __restrict__ out) {
    __shared__ uint32_t As[2][128][PAD];   // [m][k] tf32 bits
    __shared__ uint32_t Bsm[2][128][PAD];  // [n][k] tf32 bits

    const int tid  = threadIdx.x;
    const int wid  = tid >> 5;
    const int lane = tid & 31;
    const int n0   = blockIdx.x * 128;
    const int row0 = blockIdx.y * 128;
    const int b    = row0 >> 10;
    const int l0   = row0 & 1023;

    const int q = lane >> 2, r = lane & 3;
    const int wm = (wid >> 1) * 32, wn = (wid & 1) * 64;

    float ra[8], rb[8];
    auto gload = [&](int kc) {
#pragma unroll
        for (int i = 0; i < 8; ++i) {
            int e = tid + i * 256;
            int mA = e >> 4, kA = e & 15;
            ra[i] = g_yact[(size_t)(row0 + mA) * D_IN + kc + kA];
            int nB = e & 127, kB = e >> 7;
            rb[i] = W_out[(size_t)(kc + kB) * C_ + n0 + nB];
        }
    };
    auto sstore = [&](int buf) {
#pragma unroll
        for (int i = 0; i < 8; ++i) {
            int e = tid + i * 256;
            int mA = e >> 4, kA = e & 15;
            As[buf][mA][kA] = to_tf32(ra[i]);
            int nB = e & 127, kB = e >> 7;
            Bsm[buf][nB][kB] = to_tf32(rb[i]);
        }
    };

    float acc[2][8][4] = {};
    gload(0);
    sstore(0);
    __syncthreads();

    const int NIT = D_IN / 16;  // 32
    for (int it = 0; it < NIT; ++it) {
        if (it + 1 < NIT) gload((it + 1) * 16);
        int buf = it & 1;
#pragma unroll
        for (int ks = 0; ks < 2; ++ks) {
            const int kk = ks * 8;
            uint32_t af[2][4];
#pragma unroll
            for (int mt = 0; mt < 2; ++mt) {
                int base = wm + mt * 16;
                af[mt][0] = As[buf][base + q][kk + r];
                af[mt][1] = As[buf][base + q + 8][kk + r];
                af[mt][2] = As[buf][base + q][kk + r + 4];
                af[mt][3] = As[buf][base + q + 8][kk + r + 4];
            }
#pragma unroll
            for (int nt = 0; nt < 8; ++nt) {
                uint32_t bf[2];
                bf[0] = Bsm[buf][wn + nt * 8 + q][kk + r];
                bf[1] = Bsm[buf][wn + nt * 8 + q][kk + r + 4];
                mma8(acc[0][nt], af[0], bf);
                mma8(acc[1][nt], af[1], bf);
            }
        }
        if (it + 1 < NIT) sstore(buf ^ 1);
        __syncthreads();
    }

    // transposed store: out[(b*C + n)*L + l0 + m]
#pragma unroll
    for (int mt = 0; mt < 2; ++mt) {
        int m  = wm + mt * 16 + q;
#pragma unroll
        for (int nt = 0; nt < 8; ++nt) {
            int n = n0 + wn + nt * 8 + 2 * r;
            size_t p0 = (size_t)(b * C_ + n) * L_ + l0;
            size_t p1 = (size_t)(b * C_ + n + 1) * L_ + l0;
            out[p0 + m]     = acc[mt][nt][0];
            out[p1 + m]     = acc[mt][nt][1];
            out[p0 + m + 8] = acc[mt][nt][2];
            out[p1 + m + 8] = acc[mt][nt][3];
        }
    }
}

// ---------------- launch ----------------
extern "C" void kernel_launch(void* const* d_in, const int* in_sizes, int n_in,
                              void* d_out, int out_size) {
    const float* x      = (const float*)d_in[0];
    const float* ln_w   = (const float*)d_in[1];
    const float* ln_b   = (const float*)d_in[2];
    const float* W_in   = (const float*)d_in[3];
    const float* conv_w = (const float*)d_in[4];
    const float* conv_b = (const float*)d_in[5];
    const float* W_x    = (const float*)d_in[6];
    const float* W_dt   = (const float*)d_in[7];
    const float* b_dt   = (const float*)d_in[8];
    const float* A_log  = (const float*)d_in[9];
    const float* Dp     = (const float*)d_in[10];
    const float* W_out  = (const float*)d_in[11];
    float* out = (float*)d_out;

    meanvar_kernel<<<dim3(L_ / 32, B_), 256>>>(x);
    gemm1_mma_kernel<<<dim3(1024 / 128, BL / 128), 256>>>(x, ln_w, ln_b, W_in);
    conv_silu_kernel<<<BL, 512>>>(conv_w, conv_b);
    xdbl_kernel<<<BL / 32, 128>>>(W_x);
    dt_kernel<<<BL / 16, 256>>>(W_dt, b_dt);
    scan_kernel<<<512, 128>>>(A_log, Dp);
    gemm3_mma_kernel<<<dim3(C_ / 128, BL / 128), 256>>>(W_out, out);
}